// round 15
// baseline (speedup 1.0000x reference)
#include <cuda_runtime.h>
#include <cuda_fp16.h>

// Fixed shapes
#define BH_ 64
#define S_  8192
#define D_  64
#define M_  64
#define C_  65
#define TS  128
#define NT  8      // tiles per CTA

#define LOG2E 1.4426950408889634f

__device__ float g_buf1[BH_*M_*C_];

__global__ void zero_buf1_kernel() {
    int i = blockIdx.x*blockDim.x + threadIdx.x;
    if (i < BH_*M_*C_) g_buf1[i] = 0.0f;
}

__device__ __forceinline__ unsigned pack_h2(float lo, float hi) {
    __half2 h = __floats2half2_rn(lo, hi);   // x = lo, y = hi
    return *reinterpret_cast<unsigned*>(&h);
}
__device__ __forceinline__ unsigned smem_u32(const void* p) {
    unsigned a;
    asm("{ .reg .u64 t; cvta.to.shared.u64 t, %1; cvt.u32.u64 %0, t; }" : "=r"(a) : "l"(p));
    return a;
}
__device__ __forceinline__ void cp16(unsigned saddr, const float* g) {
    asm volatile("cp.async.cg.shared.global [%0], [%1], 16;"
                 :: "r"(saddr), "l"(__cvta_generic_to_global(g)));
}
#define CP_COMMIT() asm volatile("cp.async.commit_group;")
#define CP_WAIT1()  asm volatile("cp.async.wait_group 1;")
#define CP_WAIT0()  asm volatile("cp.async.wait_group 0;")

// m16n8k16 fp16 MMA, fp32 accumulate, D += A*B
__device__ __forceinline__ void mmaf16(float* c, const unsigned* a, const unsigned* b) {
    asm volatile("mma.sync.aligned.m16n8k16.row.col.f32.f16.f16.f32 "
        "{%0,%1,%2,%3}, {%4,%5,%6,%7}, {%8,%9}, {%0,%1,%2,%3};"
        : "+f"(c[0]), "+f"(c[1]), "+f"(c[2]), "+f"(c[3])
        : "r"(a[0]), "r"(a[1]), "r"(a[2]), "r"(a[3]), "r"(b[0]), "r"(b[1]));
}

// Strides (32-bit words)
#define STRX 72   // raw fp32 tiles (K/V/Q)
#define STRO 36   // half2-packed over K-dim: sOM, qP, sB1
#define STRT 68   // half2-packed over s: kT, vT

// Phase K word offsets (kT/vT double-buffered; 226816 B, 1 CTA/SM)
#define KOF_OM  0u
#define KOF_X0  2432u
#define KOF_X1  (KOF_X0 + 128u*STRX)     // 11648
#define KOF_V0  (KOF_X1 + 128u*STRX)     // 20864
#define KOF_V1  (KOF_V0 + 128u*STRX)     // 30080
#define KOF_KT0 (KOF_V1 + 128u*STRX)     // 39296  [64][68]
#define KOF_KT1 (KOF_KT0 + 64u*STRT)     // 43648
#define KOF_VT0 (KOF_KT1 + 64u*STRT)     // 48000
#define KOF_VT1 (KOF_VT0 + 64u*STRT)     // 52352
#define PK_WORDS (KOF_VT1 + 64u*STRT)    // 56704 words = 226816 B

// Phase Q word offsets (112 KB -> 2 CTAs/SM)
#define QOF_OM 0u
#define QOF_X0 2432u
#define QOF_X1 (QOF_X0 + 128u*STRX)
#define QOF_QP (QOF_X1 + 128u*STRX)      // [128][36]
#define QOF_B1 (QOF_QP + 128u*STRO)      // [72][36]
#define PQ_WORDS (QOF_B1 + 72u*STRO)

// One 128x64 fp32 tile, 16 cp.async per thread (128 threads, coalesced)
__device__ __forceinline__ void issue_tile(const float* g, unsigned sbase, int tid) {
#pragma unroll
    for (int j = 0; j < 16; ++j) {
        int l = j*128 + tid;
        int row = l >> 4, ch = l & 15;
        cp16(sbase + (unsigned)(row*STRX + ch*4)*4u, g + row*64 + ch*4);
    }
}

// omTh[m][j] = half2{ LOG2E*Om[2j][m], LOG2E*Om[2j+1][m] }  (pre-scaled for exp2)
__device__ __forceinline__ void setup_om(unsigned* sOM, const float* Og, int tid) {
    for (int i = tid; i < 2048; i += 128) {
        int m = i >> 5, j = i & 31;
        sOM[m*STRO + j] = pack_h2(LOG2E*Og[(2*j)*64 + m], LOG2E*Og[(2*j+1)*64 + m]);
    }
}

// ---------------------------------------------------------------------------
// Phase K: grid (64, 8), 128 threads, software-pipelined: 1 sync per tile.
// Tile t body: [sync] -> scatter vT[b](t), hv(t), GEMM1(t), GEMM2(t-1) from
// opposite-parity buffers, exp2 -> kT[b](t). Final GEMM2 in epilogue.
// ---------------------------------------------------------------------------
__global__ void __launch_bounds__(128)
pk_kernel(const float* __restrict__ Kg, const float* __restrict__ Vg,
          const float* __restrict__ Og)
{
    extern __shared__ unsigned sm[];
    unsigned* sOM = sm + KOF_OM;
    float*    sX[2] = { (float*)(sm + KOF_X0), (float*)(sm + KOF_X1) };
    float*    sV[2] = { (float*)(sm + KOF_V0), (float*)(sm + KOF_V1) };
    unsigned* kT[2] = { sm + KOF_KT0, sm + KOF_KT1 };
    unsigned* vT[2] = { sm + KOF_VT0, sm + KOF_VT1 };
    const unsigned xb[2] = { smem_u32(sm + KOF_X0), smem_u32(sm + KOF_X1) };
    const unsigned vb[2] = { smem_u32(sm + KOF_V0), smem_u32(sm + KOF_V1) };

    const int tid = threadIdx.x, w = tid >> 5, lane = tid & 31;
    const int gr = lane >> 2, tg = lane & 3;
    const int bh = blockIdx.x, sp = blockIdx.y;

    setup_om(sOM, Og, tid);

    float acc[9][4];
#pragma unroll
    for (int nb = 0; nb < 9; ++nb)
#pragma unroll
        for (int q = 0; q < 4; ++q) acc[nb][q] = 0.f;

    // Constant B-fragment for the [1|0..0] block (c=64..71)
    const unsigned bcn = (gr == 0) ? 0x3C003C00u : 0u;

    const size_t base0 = ((size_t)bh*S_ + (size_t)(sp*NT)*TS) * D_;
    issue_tile(Kg + base0, xb[0], tid);
    issue_tile(Vg + base0, vb[0], tid);
    CP_COMMIT();

    __syncthreads();  // sOM visible block-wide

    // Hoist omega A-fragments (loop-invariant): omr[kst][mb][q], 64 regs
    unsigned omr[4][4][4];
#pragma unroll
    for (int kst = 0; kst < 4; ++kst)
#pragma unroll
        for (int mb = 0; mb < 4; ++mb) {
            omr[kst][mb][0] = sOM[(mb*16+gr)*STRO   + kst*8 + tg];
            omr[kst][mb][1] = sOM[(mb*16+gr+8)*STRO + kst*8 + tg];
            omr[kst][mb][2] = sOM[(mb*16+gr)*STRO   + kst*8 + 4 + tg];
            omr[kst][mb][3] = sOM[(mb*16+gr+8)*STRO + kst*8 + 4 + tg];
        }

    for (int t = 0; t < NT; ++t) {
        const int b = t & 1;
        CP_WAIT0();        // tile t raw data landed (only group in flight)
        __syncthreads();   // ALL warps done with iteration t-1 reads/writes

        // cp.async for t+1 issued AFTER the barrier (its dst was read by
        // GEMM1(t-1), unguarded until the barrier above)
        if (t + 1 < NT) {
            const size_t noff = base0 + (size_t)(t+1)*TS*D_;
            issue_tile(Kg + noff, xb[b^1], tid);
            issue_tile(Vg + noff, vb[b^1], tid);
            CP_COMMIT();
        }

        // hv for own row (registers; exchanged by shuffle later)
        float hv;
        {
            const float4* rp = (const float4*)(sX[b] + tid*STRX);
            float ss = 0.f;
#pragma unroll
            for (int j = 0; j < 16; ++j) {
                float4 x = rp[j];
                ss += x.x*x.x + x.y*x.y + x.z*x.z + x.w*x.w;
            }
            hv = fmaf(ss, -0.5f*LOG2E, -3.0f);
        }
        // V^T 16-bit scatter into vT[b]
        {
            const float4* vp = (const float4*)(sV[b] + tid*STRX);
            __half* vh = (__half*)vT[b];
#pragma unroll
            for (int j = 0; j < 16; ++j) {
                float4 v = vp[j];
                vh[(4*j+0)*(2*STRT) + tid] = __float2half_rn(v.x);
                vh[(4*j+1)*(2*STRT) + tid] = __float2half_rn(v.y);
                vh[(4*j+2)*(2*STRT) + tid] = __float2half_rn(v.z);
                vh[(4*j+3)*(2*STRT) + tid] = __float2half_rn(v.w);
            }
        }

        // GEMM1^T: projL[m=64][s=128]; warp w owns s-cols 32w..+31
        float c1[4][4][4];
#pragma unroll
        for (int mb = 0; mb < 4; ++mb)
#pragma unroll
            for (int nb = 0; nb < 4; ++nb)
#pragma unroll
                for (int q = 0; q < 4; ++q) c1[mb][nb][q] = 0.f;

#pragma unroll
        for (int kst = 0; kst < 4; ++kst) {
#pragma unroll
            for (int nb = 0; nb < 4; ++nb) {
                int s = w*32 + nb*8 + gr;
                float2 x0 = *(const float2*)(sX[b] + s*STRX + kst*16 + 2*tg);
                float2 x1 = *(const float2*)(sX[b] + s*STRX + kst*16 + 2*tg + 8);
                unsigned bb[2] = { pack_h2(x0.x, x0.y), pack_h2(x1.x, x1.y) };
#pragma unroll
                for (int mb = 0; mb < 4; ++mb) mmaf16(c1[mb][nb], omr[kst][mb], bb);
            }
        }

        // GEMM2 for tile t-1 (opposite-parity buffers) — fills GEMM1/MUFU latency
        if (t > 0) {
            const unsigned* kTo = kT[b^1];
            const unsigned* vTo = vT[b^1];
#pragma unroll
            for (int kst = 0; kst < 8; ++kst) {
                unsigned a[4];
                a[0] = kTo[(w*16+gr)*STRT   + kst*8 + tg];
                a[1] = kTo[(w*16+gr+8)*STRT + kst*8 + tg];
                a[2] = kTo[(w*16+gr)*STRT   + kst*8 + 4 + tg];
                a[3] = kTo[(w*16+gr+8)*STRT + kst*8 + 4 + tg];
#pragma unroll
                for (int nb = 0; nb < 8; ++nb) {
                    unsigned bb[2] = { vTo[(nb*8+gr)*STRT + kst*8 + tg],
                                       vTo[(nb*8+gr)*STRT + kst*8 + 4 + tg] };
                    mmaf16(acc[nb], a, bb);
                }
                { unsigned bc[2] = { bcn, bcn }; mmaf16(acc[8], a, bc); }
            }
        }

        // k' = exp2(projL + hv): s-pairs -> kT[b][m][s/2]
#pragma unroll
        for (int nb = 0; nb < 4; ++nb) {
            int l0 = nb*8 + 2*tg;
            float hv0 = __shfl_sync(0xffffffffu, hv, l0);
            float hv1 = __shfl_sync(0xffffffffu, hv, l0 + 1);
            int spx = w*16 + nb*4 + tg;
#pragma unroll
            for (int mb = 0; mb < 4; ++mb) {
                int m = mb*16 + gr;
                kT[b][m*STRT + spx]     = pack_h2(exp2f(c1[mb][nb][0] + hv0), exp2f(c1[mb][nb][1] + hv1));
                kT[b][(m+8)*STRT + spx] = pack_h2(exp2f(c1[mb][nb][2] + hv0), exp2f(c1[mb][nb][3] + hv1));
            }
        }
    }

    // Epilogue: GEMM2 for the last tile
    __syncthreads();
    {
        const int b = (NT-1) & 1;
        const unsigned* kTo = kT[b];
        const unsigned* vTo = vT[b];
#pragma unroll
        for (int kst = 0; kst < 8; ++kst) {
            unsigned a[4];
            a[0] = kTo[(w*16+gr)*STRT   + kst*8 + tg];
            a[1] = kTo[(w*16+gr+8)*STRT + kst*8 + tg];
            a[2] = kTo[(w*16+gr)*STRT   + kst*8 + 4 + tg];
            a[3] = kTo[(w*16+gr+8)*STRT + kst*8 + 4 + tg];
#pragma unroll
            for (int nb = 0; nb < 8; ++nb) {
                unsigned bb[2] = { vTo[(nb*8+gr)*STRT + kst*8 + tg],
                                   vTo[(nb*8+gr)*STRT + kst*8 + 4 + tg] };
                mmaf16(acc[nb], a, bb);
            }
            { unsigned bc[2] = { bcn, bcn }; mmaf16(acc[8], a, bc); }
        }
    }

    // Fold into global buf1
    float* b1 = g_buf1 + (size_t)bh*(M_*C_);
    const int m = w*16 + gr;
#pragma unroll
    for (int nb = 0; nb < 9; ++nb) {
        int col = nb*8 + 2*tg;
        if (col < C_) {
            atomicAdd(&b1[m*C_ + col],     acc[nb][0]);
            atomicAdd(&b1[(m+8)*C_ + col], acc[nb][2]);
        }
        if (col + 1 < C_) {
            atomicAdd(&b1[m*C_ + col + 1],     acc[nb][1]);
            atomicAdd(&b1[(m+8)*C_ + col + 1], acc[nb][3]);
        }
    }
}

// ---------------------------------------------------------------------------
// Phase Q: grid (64, 8), 128 threads, 2 CTAs/SM. 2 syncs/tile:
// direct STG of divided result (fragment cols are 32B-sector aligned).
// ---------------------------------------------------------------------------
__global__ void __launch_bounds__(128)
pq_kernel(const float* __restrict__ Qg, float* __restrict__ Out,
          const float* __restrict__ Og)
{
    extern __shared__ unsigned sm[];
    unsigned* sOM = sm + QOF_OM;
    float*    sX[2] = { (float*)(sm + QOF_X0), (float*)(sm + QOF_X1) };
    unsigned* qP = sm + QOF_QP;
    unsigned* sB1 = sm + QOF_B1;
    const unsigned xb[2] = { smem_u32(sm + QOF_X0), smem_u32(sm + QOF_X1) };

    const int tid = threadIdx.x, w = tid >> 5, lane = tid & 31;
    const int gr = lane >> 2, tg = lane & 3;
    const int bh = blockIdx.x, sp = blockIdx.y;

    setup_om(sOM, Og, tid);
    // B1h[c][j] = half2{ buf1[2j][c], buf1[2j+1][c] }; c>=65 zero
    const float* b1g = g_buf1 + (size_t)bh*(M_*C_);
    for (int i = tid; i < 72*32; i += 128) {
        int c = i >> 5, j = i & 31;
        unsigned v = 0u;
        if (c < C_) v = pack_h2(b1g[(2*j)*C_ + c], b1g[(2*j+1)*C_ + c]);
        sB1[c*STRO + j] = v;
    }

    const size_t base0 = ((size_t)bh*S_ + (size_t)(sp*NT)*TS) * D_;
    issue_tile(Qg + base0, xb[0], tid);
    CP_COMMIT();

    __syncthreads();  // sB1 visible block-wide

    // Hoist buf1 B-fragments (loop-invariant): b1r[kst][nb][2], 72 regs
    unsigned b1r[4][9][2];
#pragma unroll
    for (int kst = 0; kst < 4; ++kst)
#pragma unroll
        for (int nb = 0; nb < 9; ++nb) {
            b1r[kst][nb][0] = sB1[(nb*8+gr)*STRO + kst*8 + tg];
            b1r[kst][nb][1] = sB1[(nb*8+gr)*STRO + kst*8 + 4 + tg];
        }

    for (int t = 0; t < NT; ++t) {
        const int b = t & 1;
        if (t + 1 < NT) {
            issue_tile(Qg + base0 + (size_t)(t+1)*TS*D_, xb[b^1], tid);
            CP_COMMIT();
            CP_WAIT1();
        } else {
            CP_WAIT0();
        }
        __syncthreads();   // X(t) visible; GEMM1(t-1) reads of sX[b^1] done

        // GEMM1: q'[s=128][m=64]; warp w rows 32w..+31
        {
            float cq[2][8][4];
#pragma unroll
            for (int mb = 0; mb < 2; ++mb)
#pragma unroll
                for (int nb = 0; nb < 8; ++nb)
#pragma unroll
                    for (int q = 0; q < 4; ++q) cq[mb][nb][q] = 0.f;

#pragma unroll
            for (int kst = 0; kst < 4; ++kst) {
                unsigned a[2][4];
#pragma unroll
                for (int mb = 0; mb < 2; ++mb) {
                    int row = w*32 + mb*16 + gr;
                    float2 p0 = *(const float2*)(sX[b] + row*STRX     + kst*16 + 2*tg);
                    float2 p1 = *(const float2*)(sX[b] + (row+8)*STRX + kst*16 + 2*tg);
                    float2 p2 = *(const float2*)(sX[b] + row*STRX     + kst*16 + 2*tg + 8);
                    float2 p3 = *(const float2*)(sX[b] + (row+8)*STRX + kst*16 + 2*tg + 8);
                    a[mb][0] = pack_h2(p0.x, p0.y);
                    a[mb][1] = pack_h2(p1.x, p1.y);
                    a[mb][2] = pack_h2(p2.x, p2.y);
                    a[mb][3] = pack_h2(p3.x, p3.y);
                }
#pragma unroll
                for (int nb = 0; nb < 8; ++nb) {
                    unsigned bb[2] = { sOM[(nb*8+gr)*STRO + kst*8 + tg],
                                       sOM[(nb*8+gr)*STRO + kst*8 + 4 + tg] };
                    mmaf16(cq[0][nb], a[0], bb);
                    mmaf16(cq[1][nb], a[1], bb);
                }
            }
            // q' = exp2(projL): m-pairs -> qP[s][m/2]
#pragma unroll
            for (int mb = 0; mb < 2; ++mb) {
                int row = w*32 + mb*16 + gr;
#pragma unroll
                for (int nb = 0; nb < 8; ++nb) {
                    int mp = nb*4 + tg;
                    qP[row*STRO + mp]     = pack_h2(exp2f(cq[mb][nb][0]), exp2f(cq[mb][nb][1]));
                    qP[(row+8)*STRO + mp] = pack_h2(exp2f(cq[mb][nb][2]), exp2f(cq[mb][nb][3]));
                }
            }
        }
        __syncthreads();   // qP complete; sX[b] reads all done

        // GEMM3: D[s][c=72] = q' x buf1 over m=64 (4 k16 steps, B from regs)
        float dq[2][9][4];
#pragma unroll
        for (int mb = 0; mb < 2; ++mb)
#pragma unroll
            for (int nb = 0; nb < 9; ++nb)
#pragma unroll
                for (int q = 0; q < 4; ++q) dq[mb][nb][q] = 0.f;

#pragma unroll
        for (int kst = 0; kst < 4; ++kst) {
            unsigned a[2][4];
#pragma unroll
            for (int mb = 0; mb < 2; ++mb) {
                int row = w*32 + mb*16 + gr;
                a[mb][0] = qP[row*STRO     + kst*8 + tg];
                a[mb][1] = qP[(row+8)*STRO + kst*8 + tg];
                a[mb][2] = qP[row*STRO     + kst*8 + 4 + tg];
                a[mb][3] = qP[(row+8)*STRO + kst*8 + 4 + tg];
            }
#pragma unroll
            for (int nb = 0; nb < 9; ++nb) {
                mmaf16(dq[0][nb], a[0], b1r[kst][nb]);
                mmaf16(dq[1][nb], a[1], b1r[kst][nb]);
            }
        }

        // divide by denominator (c=64: nb=8 subcol 0), direct STG (sector-aligned)
        float* ob = Out + base0 + (size_t)t*TS*D_;
#pragma unroll
        for (int mb = 0; mb < 2; ++mb) {
            int row = w*32 + mb*16 + gr;
            float den0 = __shfl_sync(0xffffffffu, dq[mb][8][0], lane & 28);
            float den8 = __shfl_sync(0xffffffffu, dq[mb][8][2], lane & 28);
            float inv0 = 1.0f / den0, inv8 = 1.0f / den8;
#pragma unroll
            for (int nb = 0; nb < 8; ++nb) {
                int col = nb*8 + 2*tg;
                float2 o0, o8;
                o0.x = dq[mb][nb][0]*inv0; o0.y = dq[mb][nb][1]*inv0;
                o8.x = dq[mb][nb][2]*inv8; o8.y = dq[mb][nb][3]*inv8;
                *(float2*)(ob + (size_t)row*D_ + col)     = o0;
                *(float2*)(ob + (size_t)(row+8)*D_ + col) = o8;
            }
        }
        // no trailing syncs: loop-top barrier separates qP/sX reuse
    }
}

extern "C" void kernel_launch(void* const* d_in, const int* in_sizes, int n_in,
                              void* d_out, int out_size)
{
    const float* Q  = (const float*)d_in[0];
    const float* K  = (const float*)d_in[1];
    const float* V  = (const float*)d_in[2];
    const float* Om = (const float*)d_in[3];
    float* out = (float*)d_out;
    (void)in_sizes; (void)n_in; (void)out_size;

    const int SMEM_K = PK_WORDS * 4;
    const int SMEM_Q = PQ_WORDS * 4;
    cudaFuncSetAttribute(pk_kernel, cudaFuncAttributeMaxDynamicSharedMemorySize, SMEM_K);
    cudaFuncSetAttribute(pq_kernel, cudaFuncAttributeMaxDynamicSharedMemorySize, SMEM_Q);

    zero_buf1_kernel<<<(BH_*M_*C_ + 255)/256, 256>>>();
    pk_kernel<<<dim3(BH_, S_/(TS*NT)), 128, SMEM_K>>>(K, V, Om);
    pq_kernel<<<dim3(BH_, S_/(TS*NT)), 128, SMEM_Q>>>(Q, out, Om);
}

// round 16
// speedup vs baseline: 1.0807x; 1.0807x over previous
#include <cuda_runtime.h>
#include <cuda_fp16.h>

// Fixed shapes
#define BH_ 64
#define S_  8192
#define D_  64
#define M_  64
#define C_  65
#define TS  128
#define NT  8      // tiles per CTA

#define LOG2E 1.4426950408889634f

__device__ float g_buf1[BH_*M_*C_];

__global__ void zero_buf1_kernel() {
    int i = blockIdx.x*blockDim.x + threadIdx.x;
    if (i < BH_*M_*C_) g_buf1[i] = 0.0f;
}

__device__ __forceinline__ unsigned pack_h2(float lo, float hi) {
    __half2 h = __floats2half2_rn(lo, hi);   // x = lo, y = hi
    return *reinterpret_cast<unsigned*>(&h);
}
__device__ __forceinline__ unsigned smem_u32(const void* p) {
    unsigned a;
    asm("{ .reg .u64 t; cvta.to.shared.u64 t, %1; cvt.u32.u64 %0, t; }" : "=r"(a) : "l"(p));
    return a;
}
__device__ __forceinline__ void cp16(unsigned saddr, const float* g) {
    asm volatile("cp.async.cg.shared.global [%0], [%1], 16;"
                 :: "r"(saddr), "l"(__cvta_generic_to_global(g)));
}
#define CP_COMMIT() asm volatile("cp.async.commit_group;")
#define CP_WAIT1()  asm volatile("cp.async.wait_group 1;")
#define CP_WAIT0()  asm volatile("cp.async.wait_group 0;")

// m16n8k16 fp16 MMA, fp32 accumulate, D += A*B
__device__ __forceinline__ void mmaf16(float* c, const unsigned* a, const unsigned* b) {
    asm volatile("mma.sync.aligned.m16n8k16.row.col.f32.f16.f16.f32 "
        "{%0,%1,%2,%3}, {%4,%5,%6,%7}, {%8,%9}, {%0,%1,%2,%3};"
        : "+f"(c[0]), "+f"(c[1]), "+f"(c[2]), "+f"(c[3])
        : "r"(a[0]), "r"(a[1]), "r"(a[2]), "r"(a[3]), "r"(b[0]), "r"(b[1]));
}

// Strides (32-bit words)
#define STRX 72   // raw fp32 tiles (K/V/Q)
#define STRO 36   // half2-packed over K-dim: sOM, qP, sB1
#define STRT 68   // half2-packed over s: kT, vT

// Phase K word offsets (R14 layout: single kT/vT; 192000 B, 1 CTA/SM)
#define KOF_OM 0u
#define KOF_X0 2432u
#define KOF_X1 (KOF_X0 + 128u*STRX)
#define KOF_V0 (KOF_X1 + 128u*STRX)
#define KOF_V1 (KOF_V0 + 128u*STRX)
#define KOF_KT (KOF_V1 + 128u*STRX)          // [64][68]
#define KOF_VT (KOF_KT + 64u*STRT)           // [64][68]
#define PK_WORDS (KOF_VT + 64u*STRT)

// Phase Q word offsets (112 KB -> 2 CTAs/SM)
#define QOF_OM 0u
#define QOF_X0 2432u
#define QOF_X1 (QOF_X0 + 128u*STRX)
#define QOF_QP (QOF_X1 + 128u*STRX)          // [128][36]
#define QOF_B1 (QOF_QP + 128u*STRO)          // [72][36]
#define PQ_WORDS (QOF_B1 + 72u*STRO)

// One 128x64 fp32 tile, 16 cp.async per thread (128 threads, coalesced)
__device__ __forceinline__ void issue_tile(const float* g, unsigned sbase, int tid) {
#pragma unroll
    for (int j = 0; j < 16; ++j) {
        int l = j*128 + tid;
        int row = l >> 4, ch = l & 15;
        cp16(sbase + (unsigned)(row*STRX + ch*4)*4u, g + row*64 + ch*4);
    }
}

// omTh[m][j] = half2{ LOG2E*Om[2j][m], LOG2E*Om[2j+1][m] }  (pre-scaled for exp2)
__device__ __forceinline__ void setup_om(unsigned* sOM, const float* Og, int tid) {
    for (int i = tid; i < 2048; i += 128) {
        int m = i >> 5, j = i & 31;
        sOM[m*STRO + j] = pack_h2(LOG2E*Og[(2*j)*64 + m], LOG2E*Og[(2*j+1)*64 + m]);
    }
}

// ---------------------------------------------------------------------------
// Phase K: R14 verbatim. 2 syncs/tile, exp2 folding, shuffle-h, reg-hoisted Ω.
// ---------------------------------------------------------------------------
__global__ void __launch_bounds__(128)
pk_kernel(const float* __restrict__ Kg, const float* __restrict__ Vg,
          const float* __restrict__ Og)
{
    extern __shared__ unsigned sm[];
    unsigned* sOM = sm + KOF_OM;
    float*    sX[2] = { (float*)(sm + KOF_X0), (float*)(sm + KOF_X1) };
    float*    sV[2] = { (float*)(sm + KOF_V0), (float*)(sm + KOF_V1) };
    unsigned* kT = sm + KOF_KT;
    unsigned* vT = sm + KOF_VT;
    const unsigned xb[2] = { smem_u32(sm + KOF_X0), smem_u32(sm + KOF_X1) };
    const unsigned vb[2] = { smem_u32(sm + KOF_V0), smem_u32(sm + KOF_V1) };

    const int tid = threadIdx.x, w = tid >> 5, lane = tid & 31;
    const int gr = lane >> 2, tg = lane & 3;
    const int bh = blockIdx.x, sp = blockIdx.y;

    setup_om(sOM, Og, tid);

    float acc[9][4];
#pragma unroll
    for (int nb = 0; nb < 9; ++nb)
#pragma unroll
        for (int q = 0; q < 4; ++q) acc[nb][q] = 0.f;

    const unsigned bcn = (gr == 0) ? 0x3C003C00u : 0u;

    const size_t base0 = ((size_t)bh*S_ + (size_t)(sp*NT)*TS) * D_;
    issue_tile(Kg + base0, xb[0], tid);
    issue_tile(Vg + base0, vb[0], tid);
    CP_COMMIT();

    __syncthreads();  // sOM visible block-wide

    unsigned omr[4][4][4];
#pragma unroll
    for (int kst = 0; kst < 4; ++kst)
#pragma unroll
        for (int mb = 0; mb < 4; ++mb) {
            omr[kst][mb][0] = sOM[(mb*16+gr)*STRO   + kst*8 + tg];
            omr[kst][mb][1] = sOM[(mb*16+gr+8)*STRO + kst*8 + tg];
            omr[kst][mb][2] = sOM[(mb*16+gr)*STRO   + kst*8 + 4 + tg];
            omr[kst][mb][3] = sOM[(mb*16+gr+8)*STRO + kst*8 + 4 + tg];
        }

    for (int t = 0; t < NT; ++t) {
        const int b = t & 1;
        if (t + 1 < NT) {
            const size_t noff = base0 + (size_t)(t+1)*TS*D_;
            issue_tile(Kg + noff, xb[b^1], tid);
            issue_tile(Vg + noff, vb[b^1], tid);
            CP_COMMIT();
            CP_WAIT1();
        } else {
            CP_WAIT0();
        }
        __syncthreads();   // X/V(t) visible; GEMM2(t-1) done (kT/vT/sX/sV free)

        float hv;
        {
            const float4* rp = (const float4*)(sX[b] + tid*STRX);
            float ss = 0.f;
#pragma unroll
            for (int j = 0; j < 16; ++j) {
                float4 x = rp[j];
                ss += x.x*x.x + x.y*x.y + x.z*x.z + x.w*x.w;
            }
            hv = fmaf(ss, -0.5f*LOG2E, -3.0f);
        }
        {
            const float4* vp = (const float4*)(sV[b] + tid*STRX);
            __half* vh = (__half*)vT;
#pragma unroll
            for (int j = 0; j < 16; ++j) {
                float4 v = vp[j];
                vh[(4*j+0)*(2*STRT) + tid] = __float2half_rn(v.x);
                vh[(4*j+1)*(2*STRT) + tid] = __float2half_rn(v.y);
                vh[(4*j+2)*(2*STRT) + tid] = __float2half_rn(v.z);
                vh[(4*j+3)*(2*STRT) + tid] = __float2half_rn(v.w);
            }
        }

        float c1[4][4][4];
#pragma unroll
        for (int mb = 0; mb < 4; ++mb)
#pragma unroll
            for (int nb = 0; nb < 4; ++nb)
#pragma unroll
                for (int q = 0; q < 4; ++q) c1[mb][nb][q] = 0.f;

#pragma unroll
        for (int kst = 0; kst < 4; ++kst) {
#pragma unroll
            for (int nb = 0; nb < 4; ++nb) {
                int s = w*32 + nb*8 + gr;
                float2 x0 = *(const float2*)(sX[b] + s*STRX + kst*16 + 2*tg);
                float2 x1 = *(const float2*)(sX[b] + s*STRX + kst*16 + 2*tg + 8);
                unsigned bb[2] = { pack_h2(x0.x, x0.y), pack_h2(x1.x, x1.y) };
#pragma unroll
                for (int mb = 0; mb < 4; ++mb) mmaf16(c1[mb][nb], omr[kst][mb], bb);
            }
        }
#pragma unroll
        for (int nb = 0; nb < 4; ++nb) {
            int l0 = nb*8 + 2*tg;
            float hv0 = __shfl_sync(0xffffffffu, hv, l0);
            float hv1 = __shfl_sync(0xffffffffu, hv, l0 + 1);
            int spx = w*16 + nb*4 + tg;
#pragma unroll
            for (int mb = 0; mb < 4; ++mb) {
                int m = mb*16 + gr;
                kT[m*STRT + spx]     = pack_h2(exp2f(c1[mb][nb][0] + hv0), exp2f(c1[mb][nb][1] + hv1));
                kT[(m+8)*STRT + spx] = pack_h2(exp2f(c1[mb][nb][2] + hv0), exp2f(c1[mb][nb][3] + hv1));
            }
        }
        __syncthreads();   // kT/vT complete block-wide

#pragma unroll
        for (int kst = 0; kst < 8; ++kst) {
            unsigned a[4];
            a[0] = kT[(w*16+gr)*STRT   + kst*8 + tg];
            a[1] = kT[(w*16+gr+8)*STRT + kst*8 + tg];
            a[2] = kT[(w*16+gr)*STRT   + kst*8 + 4 + tg];
            a[3] = kT[(w*16+gr+8)*STRT + kst*8 + 4 + tg];
#pragma unroll
            for (int nb = 0; nb < 8; ++nb) {
                unsigned bb[2] = { vT[(nb*8+gr)*STRT + kst*8 + tg],
                                   vT[(nb*8+gr)*STRT + kst*8 + 4 + tg] };
                mmaf16(acc[nb], a, bb);
            }
            { unsigned bc[2] = { bcn, bcn }; mmaf16(acc[8], a, bc); }
        }
    }

    float* b1 = g_buf1 + (size_t)bh*(M_*C_);
    const int m = w*16 + gr;
#pragma unroll
    for (int nb = 0; nb < 9; ++nb) {
        int col = nb*8 + 2*tg;
        if (col < C_) {
            atomicAdd(&b1[m*C_ + col],     acc[nb][0]);
            atomicAdd(&b1[(m+8)*C_ + col], acc[nb][2]);
        }
        if (col + 1 < C_) {
            atomicAdd(&b1[m*C_ + col + 1],     acc[nb][1]);
            atomicAdd(&b1[(m+8)*C_ + col + 1], acc[nb][3]);
        }
    }
}

// ---------------------------------------------------------------------------
// Phase Q: 2 syncs/tile, direct float2 STG of divided result (sector-aligned).
// ---------------------------------------------------------------------------
__global__ void __launch_bounds__(128)
pq_kernel(const float* __restrict__ Qg, float* __restrict__ Out,
          const float* __restrict__ Og)
{
    extern __shared__ unsigned sm[];
    unsigned* sOM = sm + QOF_OM;
    float*    sX[2] = { (float*)(sm + QOF_X0), (float*)(sm + QOF_X1) };
    unsigned* qP = sm + QOF_QP;
    unsigned* sB1 = sm + QOF_B1;
    const unsigned xb[2] = { smem_u32(sm + QOF_X0), smem_u32(sm + QOF_X1) };

    const int tid = threadIdx.x, w = tid >> 5, lane = tid & 31;
    const int gr = lane >> 2, tg = lane & 3;
    const int bh = blockIdx.x, sp = blockIdx.y;

    setup_om(sOM, Og, tid);
    const float* b1g = g_buf1 + (size_t)bh*(M_*C_);
    for (int i = tid; i < 72*32; i += 128) {
        int c = i >> 5, j = i & 31;
        unsigned v = 0u;
        if (c < C_) v = pack_h2(b1g[(2*j)*C_ + c], b1g[(2*j+1)*C_ + c]);
        sB1[c*STRO + j] = v;
    }

    const size_t base0 = ((size_t)bh*S_ + (size_t)(sp*NT)*TS) * D_;
    issue_tile(Qg + base0, xb[0], tid);
    CP_COMMIT();

    __syncthreads();  // sB1 visible block-wide

    unsigned b1r[4][9][2];
#pragma unroll
    for (int kst = 0; kst < 4; ++kst)
#pragma unroll
        for (int nb = 0; nb < 9; ++nb) {
            b1r[kst][nb][0] = sB1[(nb*8+gr)*STRO + kst*8 + tg];
            b1r[kst][nb][1] = sB1[(nb*8+gr)*STRO + kst*8 + 4 + tg];
        }

    for (int t = 0; t < NT; ++t) {
        const int b = t & 1;
        if (t + 1 < NT) {
            issue_tile(Qg + base0 + (size_t)(t+1)*TS*D_, xb[b^1], tid);
            CP_COMMIT();
            CP_WAIT1();
        } else {
            CP_WAIT0();
        }
        __syncthreads();   // X(t) visible; GEMM3(t-1) qP reads done

        // GEMM1: q'[s=128][m=64]; warp w rows 32w..+31
        {
            float cq[2][8][4];
#pragma unroll
            for (int mb = 0; mb < 2; ++mb)
#pragma unroll
                for (int nb = 0; nb < 8; ++nb)
#pragma unroll
                    for (int q = 0; q < 4; ++q) cq[mb][nb][q] = 0.f;

#pragma unroll
            for (int kst = 0; kst < 4; ++kst) {
                unsigned a[2][4];
#pragma unroll
                for (int mb = 0; mb < 2; ++mb) {
                    int row = w*32 + mb*16 + gr;
                    float2 p0 = *(const float2*)(sX[b] + row*STRX     + kst*16 + 2*tg);
                    float2 p1 = *(const float2*)(sX[b] + (row+8)*STRX + kst*16 + 2*tg);
                    float2 p2 = *(const float2*)(sX[b] + row*STRX     + kst*16 + 2*tg + 8);
                    float2 p3 = *(const float2*)(sX[b] + (row+8)*STRX + kst*16 + 2*tg + 8);
                    a[mb][0] = pack_h2(p0.x, p0.y);
                    a[mb][1] = pack_h2(p1.x, p1.y);
                    a[mb][2] = pack_h2(p2.x, p2.y);
                    a[mb][3] = pack_h2(p3.x, p3.y);
                }
#pragma unroll
                for (int nb = 0; nb < 8; ++nb) {
                    unsigned bb[2] = { sOM[(nb*8+gr)*STRO + kst*8 + tg],
                                       sOM[(nb*8+gr)*STRO + kst*8 + 4 + tg] };
                    mmaf16(cq[0][nb], a[0], bb);
                    mmaf16(cq[1][nb], a[1], bb);
                }
            }
#pragma unroll
            for (int mb = 0; mb < 2; ++mb) {
                int row = w*32 + mb*16 + gr;
#pragma unroll
                for (int nb = 0; nb < 8; ++nb) {
                    int mp = nb*4 + tg;
                    qP[row*STRO + mp]     = pack_h2(exp2f(cq[mb][nb][0]), exp2f(cq[mb][nb][1]));
                    qP[(row+8)*STRO + mp] = pack_h2(exp2f(cq[mb][nb][2]), exp2f(cq[mb][nb][3]));
                }
            }
        }
        __syncthreads();   // qP complete; sX[b] reads all done

        // GEMM3: D[s][c=72] = q' x buf1 (B from regs)
        float dq[2][9][4];
#pragma unroll
        for (int mb = 0; mb < 2; ++mb)
#pragma unroll
            for (int nb = 0; nb < 9; ++nb)
#pragma unroll
                for (int q = 0; q < 4; ++q) dq[mb][nb][q] = 0.f;

#pragma unroll
        for (int kst = 0; kst < 4; ++kst) {
            unsigned a[2][4];
#pragma unroll
            for (int mb = 0; mb < 2; ++mb) {
                int row = w*32 + mb*16 + gr;
                a[mb][0] = qP[row*STRO     + kst*8 + tg];
                a[mb][1] = qP[(row+8)*STRO + kst*8 + tg];
                a[mb][2] = qP[row*STRO     + kst*8 + 4 + tg];
                a[mb][3] = qP[(row+8)*STRO + kst*8 + 4 + tg];
            }
#pragma unroll
            for (int nb = 0; nb < 9; ++nb) {
                mmaf16(dq[0][nb], a[0], b1r[kst][nb]);
                mmaf16(dq[1][nb], a[1], b1r[kst][nb]);
            }
        }

        // divide, direct STG (quad covers a 32B sector per nb)
        float* ob = Out + base0 + (size_t)t*TS*D_;
#pragma unroll
        for (int mb = 0; mb < 2; ++mb) {
            int row = w*32 + mb*16 + gr;
            float den0 = __shfl_sync(0xffffffffu, dq[mb][8][0], lane & 28);
            float den8 = __shfl_sync(0xffffffffu, dq[mb][8][2], lane & 28);
            float inv0 = 1.0f / den0, inv8 = 1.0f / den8;
#pragma unroll
            for (int nb = 0; nb < 8; ++nb) {
                int col = nb*8 + 2*tg;
                float2 o0, o8;
                o0.x = dq[mb][nb][0]*inv0; o0.y = dq[mb][nb][1]*inv0;
                o8.x = dq[mb][nb][2]*inv8; o8.y = dq[mb][nb][3]*inv8;
                *(float2*)(ob + (size_t)row*D_ + col)     = o0;
                *(float2*)(ob + (size_t)(row+8)*D_ + col) = o8;
            }
        }
        // loop-top barrier separates qP/sX reuse
    }
}

extern "C" void kernel_launch(void* const* d_in, const int* in_sizes, int n_in,
                              void* d_out, int out_size)
{
    const float* Q  = (const float*)d_in[0];
    const float* K  = (const float*)d_in[1];
    const float* V  = (const float*)d_in[2];
    const float* Om = (const float*)d_in[3];
    float* out = (float*)d_out;
    (void)in_sizes; (void)n_in; (void)out_size;

    const int SMEM_K = PK_WORDS * 4;
    const int SMEM_Q = PQ_WORDS * 4;
    cudaFuncSetAttribute(pk_kernel, cudaFuncAttributeMaxDynamicSharedMemorySize, SMEM_K);
    cudaFuncSetAttribute(pq_kernel, cudaFuncAttributeMaxDynamicSharedMemorySize, SMEM_Q);

    zero_buf1_kernel<<<(BH_*M_*C_ + 255)/256, 256>>>();
    pk_kernel<<<dim3(BH_, S_/(TS*NT)), 128, SMEM_K>>>(K, V, Om);
    pq_kernel<<<dim3(BH_, S_/(TS*NT)), 128, SMEM_Q>>>(Q, out, Om);
}

// round 17
// speedup vs baseline: 1.1116x; 1.0286x over previous
#include <cuda_runtime.h>
#include <cuda_fp16.h>

// Fixed shapes
#define BH_ 64
#define S_  8192
#define D_  64
#define M_  64
#define C_  65
#define TS  128
#define NT  8      // tiles per CTA

#define LOG2E 1.4426950408889634f

__device__ float g_buf1[BH_*M_*C_];

__global__ void zero_buf1_kernel() {
    int i = blockIdx.x*blockDim.x + threadIdx.x;
    if (i < BH_*M_*C_) g_buf1[i] = 0.0f;
}

__device__ __forceinline__ unsigned pack_h2(float lo, float hi) {
    __half2 h = __floats2half2_rn(lo, hi);   // x = lo, y = hi
    return *reinterpret_cast<unsigned*>(&h);
}
__device__ __forceinline__ float ex2(float x) {     // single MUFU.EX2
    float r; asm("ex2.approx.ftz.f32 %0, %1;" : "=f"(r) : "f"(x)); return r;
}
__device__ __forceinline__ float frcp(float x) {    // single MUFU.RCP
    float r; asm("rcp.approx.ftz.f32 %0, %1;" : "=f"(r) : "f"(x)); return r;
}
__device__ __forceinline__ unsigned smem_u32(const void* p) {
    unsigned a;
    asm("{ .reg .u64 t; cvta.to.shared.u64 t, %1; cvt.u32.u64 %0, t; }" : "=r"(a) : "l"(p));
    return a;
}
__device__ __forceinline__ void cp16(unsigned saddr, const float* g) {
    asm volatile("cp.async.cg.shared.global [%0], [%1], 16;"
                 :: "r"(saddr), "l"(__cvta_generic_to_global(g)));
}
#define CP_COMMIT() asm volatile("cp.async.commit_group;")
#define CP_WAIT1()  asm volatile("cp.async.wait_group 1;")
#define CP_WAIT0()  asm volatile("cp.async.wait_group 0;")

// m16n8k16 fp16 MMA, fp32 accumulate, D += A*B
__device__ __forceinline__ void mmaf16(float* c, const unsigned* a, const unsigned* b) {
    asm volatile("mma.sync.aligned.m16n8k16.row.col.f32.f16.f16.f32 "
        "{%0,%1,%2,%3}, {%4,%5,%6,%7}, {%8,%9}, {%0,%1,%2,%3};"
        : "+f"(c[0]), "+f"(c[1]), "+f"(c[2]), "+f"(c[3])
        : "r"(a[0]), "r"(a[1]), "r"(a[2]), "r"(a[3]), "r"(b[0]), "r"(b[1]));
}

// Strides (32-bit words)
#define STRX 72   // raw fp32 tiles (K/V/Q)
#define STRO 36   // half2-packed over K-dim: sOM, qP, sB1
#define STRT 68   // half2-packed over s: kT, vT

// Phase K word offsets (single kT/vT; 192000 B, 1 CTA/SM)
#define KOF_OM 0u
#define KOF_X0 2432u
#define KOF_X1 (KOF_X0 + 128u*STRX)
#define KOF_V0 (KOF_X1 + 128u*STRX)
#define KOF_V1 (KOF_V0 + 128u*STRX)
#define KOF_KT (KOF_V1 + 128u*STRX)          // [64][68]
#define KOF_VT (KOF_KT + 64u*STRT)           // [64][68]
#define PK_WORDS (KOF_VT + 64u*STRT)

// Phase Q word offsets (112 KB -> 2 CTAs/SM)
#define QOF_OM 0u
#define QOF_X0 2432u
#define QOF_X1 (QOF_X0 + 128u*STRX)
#define QOF_QP (QOF_X1 + 128u*STRX)          // [128][36]
#define QOF_B1 (QOF_QP + 128u*STRO)          // [72][36]
#define PQ_WORDS (QOF_B1 + 72u*STRO)

// One 128x64 fp32 tile, 16 cp.async per thread (128 threads, coalesced)
__device__ __forceinline__ void issue_tile(const float* g, unsigned sbase, int tid) {
#pragma unroll
    for (int j = 0; j < 16; ++j) {
        int l = j*128 + tid;
        int row = l >> 4, ch = l & 15;
        cp16(sbase + (unsigned)(row*STRX + ch*4)*4u, g + row*64 + ch*4);
    }
}

// omTh[m][j] = half2{ LOG2E*Om[2j][m], LOG2E*Om[2j+1][m] }  (pre-scaled for exp2)
__device__ __forceinline__ void setup_om(unsigned* sOM, const float* Og, int tid) {
    for (int i = tid; i < 2048; i += 128) {
        int m = i >> 5, j = i & 31;
        sOM[m*STRO + j] = pack_h2(LOG2E*Og[(2*j)*64 + m], LOG2E*Og[(2*j+1)*64 + m]);
    }
}

// ---------------------------------------------------------------------------
// Phase K: R16 skeleton; exp2f -> MUFU ex2.
// ---------------------------------------------------------------------------
__global__ void __launch_bounds__(128)
pk_kernel(const float* __restrict__ Kg, const float* __restrict__ Vg,
          const float* __restrict__ Og)
{
    extern __shared__ unsigned sm[];
    unsigned* sOM = sm + KOF_OM;
    float*    sX[2] = { (float*)(sm + KOF_X0), (float*)(sm + KOF_X1) };
    float*    sV[2] = { (float*)(sm + KOF_V0), (float*)(sm + KOF_V1) };
    unsigned* kT = sm + KOF_KT;
    unsigned* vT = sm + KOF_VT;
    const unsigned xb[2] = { smem_u32(sm + KOF_X0), smem_u32(sm + KOF_X1) };
    const unsigned vb[2] = { smem_u32(sm + KOF_V0), smem_u32(sm + KOF_V1) };

    const int tid = threadIdx.x, w = tid >> 5, lane = tid & 31;
    const int gr = lane >> 2, tg = lane & 3;
    const int bh = blockIdx.x, sp = blockIdx.y;

    setup_om(sOM, Og, tid);

    float acc[9][4];
#pragma unroll
    for (int nb = 0; nb < 9; ++nb)
#pragma unroll
        for (int q = 0; q < 4; ++q) acc[nb][q] = 0.f;

    const unsigned bcn = (gr == 0) ? 0x3C003C00u : 0u;

    const size_t base0 = ((size_t)bh*S_ + (size_t)(sp*NT)*TS) * D_;
    issue_tile(Kg + base0, xb[0], tid);
    issue_tile(Vg + base0, vb[0], tid);
    CP_COMMIT();

    __syncthreads();  // sOM visible block-wide

    unsigned omr[4][4][4];
#pragma unroll
    for (int kst = 0; kst < 4; ++kst)
#pragma unroll
        for (int mb = 0; mb < 4; ++mb) {
            omr[kst][mb][0] = sOM[(mb*16+gr)*STRO   + kst*8 + tg];
            omr[kst][mb][1] = sOM[(mb*16+gr+8)*STRO + kst*8 + tg];
            omr[kst][mb][2] = sOM[(mb*16+gr)*STRO   + kst*8 + 4 + tg];
            omr[kst][mb][3] = sOM[(mb*16+gr+8)*STRO + kst*8 + 4 + tg];
        }

    for (int t = 0; t < NT; ++t) {
        const int b = t & 1;
        if (t + 1 < NT) {
            const size_t noff = base0 + (size_t)(t+1)*TS*D_;
            issue_tile(Kg + noff, xb[b^1], tid);
            issue_tile(Vg + noff, vb[b^1], tid);
            CP_COMMIT();
            CP_WAIT1();
        } else {
            CP_WAIT0();
        }
        __syncthreads();   // X/V(t) visible; GEMM2(t-1) done (kT/vT/sX/sV free)

        float hv;
        {
            const float4* rp = (const float4*)(sX[b] + tid*STRX);
            float ss = 0.f;
#pragma unroll
            for (int j = 0; j < 16; ++j) {
                float4 x = rp[j];
                ss += x.x*x.x + x.y*x.y + x.z*x.z + x.w*x.w;
            }
            hv = fmaf(ss, -0.5f*LOG2E, -3.0f);
        }
        {
            const float4* vp = (const float4*)(sV[b] + tid*STRX);
            __half* vh = (__half*)vT;
#pragma unroll
            for (int j = 0; j < 16; ++j) {
                float4 v = vp[j];
                vh[(4*j+0)*(2*STRT) + tid] = __float2half_rn(v.x);
                vh[(4*j+1)*(2*STRT) + tid] = __float2half_rn(v.y);
                vh[(4*j+2)*(2*STRT) + tid] = __float2half_rn(v.z);
                vh[(4*j+3)*(2*STRT) + tid] = __float2half_rn(v.w);
            }
        }

        float c1[4][4][4];
#pragma unroll
        for (int mb = 0; mb < 4; ++mb)
#pragma unroll
            for (int nb = 0; nb < 4; ++nb)
#pragma unroll
                for (int q = 0; q < 4; ++q) c1[mb][nb][q] = 0.f;

#pragma unroll
        for (int kst = 0; kst < 4; ++kst) {
#pragma unroll
            for (int nb = 0; nb < 4; ++nb) {
                int s = w*32 + nb*8 + gr;
                float2 x0 = *(const float2*)(sX[b] + s*STRX + kst*16 + 2*tg);
                float2 x1 = *(const float2*)(sX[b] + s*STRX + kst*16 + 2*tg + 8);
                unsigned bb[2] = { pack_h2(x0.x, x0.y), pack_h2(x1.x, x1.y) };
#pragma unroll
                for (int mb = 0; mb < 4; ++mb) mmaf16(c1[mb][nb], omr[kst][mb], bb);
            }
        }
#pragma unroll
        for (int nb = 0; nb < 4; ++nb) {
            int l0 = nb*8 + 2*tg;
            float hv0 = __shfl_sync(0xffffffffu, hv, l0);
            float hv1 = __shfl_sync(0xffffffffu, hv, l0 + 1);
            int spx = w*16 + nb*4 + tg;
#pragma unroll
            for (int mb = 0; mb < 4; ++mb) {
                int m = mb*16 + gr;
                kT[m*STRT + spx]     = pack_h2(ex2(c1[mb][nb][0] + hv0), ex2(c1[mb][nb][1] + hv1));
                kT[(m+8)*STRT + spx] = pack_h2(ex2(c1[mb][nb][2] + hv0), ex2(c1[mb][nb][3] + hv1));
            }
        }
        __syncthreads();   // kT/vT complete block-wide

#pragma unroll
        for (int kst = 0; kst < 8; ++kst) {
            unsigned a[4];
            a[0] = kT[(w*16+gr)*STRT   + kst*8 + tg];
            a[1] = kT[(w*16+gr+8)*STRT + kst*8 + tg];
            a[2] = kT[(w*16+gr)*STRT   + kst*8 + 4 + tg];
            a[3] = kT[(w*16+gr+8)*STRT + kst*8 + 4 + tg];
#pragma unroll
            for (int nb = 0; nb < 8; ++nb) {
                unsigned bb[2] = { vT[(nb*8+gr)*STRT + kst*8 + tg],
                                   vT[(nb*8+gr)*STRT + kst*8 + 4 + tg] };
                mmaf16(acc[nb], a, bb);
            }
            { unsigned bc[2] = { bcn, bcn }; mmaf16(acc[8], a, bc); }
        }
    }

    float* b1 = g_buf1 + (size_t)bh*(M_*C_);
    const int m = w*16 + gr;
#pragma unroll
    for (int nb = 0; nb < 9; ++nb) {
        int col = nb*8 + 2*tg;
        if (col < C_) {
            atomicAdd(&b1[m*C_ + col],     acc[nb][0]);
            atomicAdd(&b1[(m+8)*C_ + col], acc[nb][2]);
        }
        if (col + 1 < C_) {
            atomicAdd(&b1[m*C_ + col + 1],     acc[nb][1]);
            atomicAdd(&b1[(m+8)*C_ + col + 1], acc[nb][3]);
        }
    }
}

// ---------------------------------------------------------------------------
// Phase Q: R16 skeleton; exp2f -> MUFU ex2, 1/x -> MUFU rcp.
// ---------------------------------------------------------------------------
__global__ void __launch_bounds__(128)
pq_kernel(const float* __restrict__ Qg, float* __restrict__ Out,
          const float* __restrict__ Og)
{
    extern __shared__ unsigned sm[];
    unsigned* sOM = sm + QOF_OM;
    float*    sX[2] = { (float*)(sm + QOF_X0), (float*)(sm + QOF_X1) };
    unsigned* qP = sm + QOF_QP;
    unsigned* sB1 = sm + QOF_B1;
    const unsigned xb[2] = { smem_u32(sm + QOF_X0), smem_u32(sm + QOF_X1) };

    const int tid = threadIdx.x, w = tid >> 5, lane = tid & 31;
    const int gr = lane >> 2, tg = lane & 3;
    const int bh = blockIdx.x, sp = blockIdx.y;

    setup_om(sOM, Og, tid);
    const float* b1g = g_buf1 + (size_t)bh*(M_*C_);
    for (int i = tid; i < 72*32; i += 128) {
        int c = i >> 5, j = i & 31;
        unsigned v = 0u;
        if (c < C_) v = pack_h2(b1g[(2*j)*C_ + c], b1g[(2*j+1)*C_ + c]);
        sB1[c*STRO + j] = v;
    }

    const size_t base0 = ((size_t)bh*S_ + (size_t)(sp*NT)*TS) * D_;
    issue_tile(Qg + base0, xb[0], tid);
    CP_COMMIT();

    __syncthreads();  // sB1 visible block-wide

    unsigned b1r[4][9][2];
#pragma unroll
    for (int kst = 0; kst < 4; ++kst)
#pragma unroll
        for (int nb = 0; nb < 9; ++nb) {
            b1r[kst][nb][0] = sB1[(nb*8+gr)*STRO + kst*8 + tg];
            b1r[kst][nb][1] = sB1[(nb*8+gr)*STRO + kst*8 + 4 + tg];
        }

    for (int t = 0; t < NT; ++t) {
        const int b = t & 1;
        if (t + 1 < NT) {
            issue_tile(Qg + base0 + (size_t)(t+1)*TS*D_, xb[b^1], tid);
            CP_COMMIT();
            CP_WAIT1();
        } else {
            CP_WAIT0();
        }
        __syncthreads();   // X(t) visible; GEMM3(t-1) qP reads done

        // GEMM1: q'[s=128][m=64]; warp w rows 32w..+31
        {
            float cq[2][8][4];
#pragma unroll
            for (int mb = 0; mb < 2; ++mb)
#pragma unroll
                for (int nb = 0; nb < 8; ++nb)
#pragma unroll
                    for (int q = 0; q < 4; ++q) cq[mb][nb][q] = 0.f;

#pragma unroll
            for (int kst = 0; kst < 4; ++kst) {
                unsigned a[2][4];
#pragma unroll
                for (int mb = 0; mb < 2; ++mb) {
                    int row = w*32 + mb*16 + gr;
                    float2 p0 = *(const float2*)(sX[b] + row*STRX     + kst*16 + 2*tg);
                    float2 p1 = *(const float2*)(sX[b] + (row+8)*STRX + kst*16 + 2*tg);
                    float2 p2 = *(const float2*)(sX[b] + row*STRX     + kst*16 + 2*tg + 8);
                    float2 p3 = *(const float2*)(sX[b] + (row+8)*STRX + kst*16 + 2*tg + 8);
                    a[mb][0] = pack_h2(p0.x, p0.y);
                    a[mb][1] = pack_h2(p1.x, p1.y);
                    a[mb][2] = pack_h2(p2.x, p2.y);
                    a[mb][3] = pack_h2(p3.x, p3.y);
                }
#pragma unroll
                for (int nb = 0; nb < 8; ++nb) {
                    unsigned bb[2] = { sOM[(nb*8+gr)*STRO + kst*8 + tg],
                                       sOM[(nb*8+gr)*STRO + kst*8 + 4 + tg] };
                    mmaf16(cq[0][nb], a[0], bb);
                    mmaf16(cq[1][nb], a[1], bb);
                }
            }
#pragma unroll
            for (int mb = 0; mb < 2; ++mb) {
                int row = w*32 + mb*16 + gr;
#pragma unroll
                for (int nb = 0; nb < 8; ++nb) {
                    int mp = nb*4 + tg;
                    qP[row*STRO + mp]     = pack_h2(ex2(cq[mb][nb][0]), ex2(cq[mb][nb][1]));
                    qP[(row+8)*STRO + mp] = pack_h2(ex2(cq[mb][nb][2]), ex2(cq[mb][nb][3]));
                }
            }
        }
        __syncthreads();   // qP complete; sX[b] reads all done

        // GEMM3: D[s][c=72] = q' x buf1 (B from regs)
        float dq[2][9][4];
#pragma unroll
        for (int mb = 0; mb < 2; ++mb)
#pragma unroll
            for (int nb = 0; nb < 9; ++nb)
#pragma unroll
                for (int q = 0; q < 4; ++q) dq[mb][nb][q] = 0.f;

#pragma unroll
        for (int kst = 0; kst < 4; ++kst) {
            unsigned a[2][4];
#pragma unroll
            for (int mb = 0; mb < 2; ++mb) {
                int row = w*32 + mb*16 + gr;
                a[mb][0] = qP[row*STRO     + kst*8 + tg];
                a[mb][1] = qP[(row+8)*STRO + kst*8 + tg];
                a[mb][2] = qP[row*STRO     + kst*8 + 4 + tg];
                a[mb][3] = qP[(row+8)*STRO + kst*8 + 4 + tg];
            }
#pragma unroll
            for (int nb = 0; nb < 9; ++nb) {
                mmaf16(dq[0][nb], a[0], b1r[kst][nb]);
                mmaf16(dq[1][nb], a[1], b1r[kst][nb]);
            }
        }

        // divide (MUFU rcp), direct STG (quad covers a 32B sector per nb)
        float* ob = Out + base0 + (size_t)t*TS*D_;
#pragma unroll
        for (int mb = 0; mb < 2; ++mb) {
            int row = w*32 + mb*16 + gr;
            float den0 = __shfl_sync(0xffffffffu, dq[mb][8][0], lane & 28);
            float den8 = __shfl_sync(0xffffffffu, dq[mb][8][2], lane & 28);
            float inv0 = frcp(den0), inv8 = frcp(den8);
#pragma unroll
            for (int nb = 0; nb < 8; ++nb) {
                int col = nb*8 + 2*tg;
                float2 o0, o8;
                o0.x = dq[mb][nb][0]*inv0; o0.y = dq[mb][nb][1]*inv0;
                o8.x = dq[mb][nb][2]*inv8; o8.y = dq[mb][nb][3]*inv8;
                *(float2*)(ob + (size_t)row*D_ + col)     = o0;
                *(float2*)(ob + (size_t)(row+8)*D_ + col) = o8;
            }
        }
        // loop-top barrier separates qP/sX reuse
    }
}

extern "C" void kernel_launch(void* const* d_in, const int* in_sizes, int n_in,
                              void* d_out, int out_size)
{
    const float* Q  = (const float*)d_in[0];
    const float* K  = (const float*)d_in[1];
    const float* V  = (const float*)d_in[2];
    const float* Om = (const float*)d_in[3];
    float* out = (float*)d_out;
    (void)in_sizes; (void)n_in; (void)out_size;

    const int SMEM_K = PK_WORDS * 4;
    const int SMEM_Q = PQ_WORDS * 4;
    cudaFuncSetAttribute(pk_kernel, cudaFuncAttributeMaxDynamicSharedMemorySize, SMEM_K);
    cudaFuncSetAttribute(pq_kernel, cudaFuncAttributeMaxDynamicSharedMemorySize, SMEM_Q);

    zero_buf1_kernel<<<(BH_*M_*C_ + 255)/256, 256>>>();
    pk_kernel<<<dim3(BH_, S_/(TS*NT)), 128, SMEM_K>>>(K, V, Om);
    pq_kernel<<<dim3(BH_, S_/(TS*NT)), 128, SMEM_Q>>>(Q, out, Om);
}